// round 1
// baseline (speedup 1.0000x reference)
#include <cuda_runtime.h>
#include <cstdint>

// Problem constants (fixed shapes)
#define BB 4
#define NN 4096
#define KK 16
#define DP 64
#define DM 128
#define EPSN 1e-8f

// ---------------- scratch (device globals; no allocation allowed) ----------
__device__ float g_q[BB*NN*DM];     // 8 MB
__device__ float g_k[BB*NN*DM];     // 8 MB
__device__ float g_v[BB*NN*DM];     // 8 MB
__device__ int   g_knn[BB*NN*KK];   // 1 MB

// ---------------- packed fp32x2 FMA (Blackwell FFMA2) ----------------------
__device__ __forceinline__ float2 ffma2(float2 a, float2 b, float2 c){
  float2 d;
  asm("fma.rn.f32x2 %0, %1, %2, %3;"
      : "=l"(reinterpret_cast<unsigned long long&>(d))
      : "l"(reinterpret_cast<unsigned long long&>(a)),
        "l"(reinterpret_cast<unsigned long long&>(b)),
        "l"(reinterpret_cast<unsigned long long&>(c)));
  return d;
}

// Core GEMM accumulate: 128 rows held column-major in smem (stride `instride`,
// even), this thread produces output column f for 64 rows starting at `base`
// (32 row-pairs). W is row-major [NCOLS][128]. Weight loads prefetched one
// group (4 c's) ahead to hide L2 latency.
template<int NCOLS>
__device__ __forceinline__ void gemm_acc(const float* __restrict__ in_sm, int instride,
                                         const float* __restrict__ W, int f, int base,
                                         float2* acc)
{
  float w[4];
#pragma unroll
  for (int u=0;u<4;++u) w[u] = (u < NCOLS) ? W[u*DM + f] : 0.f;
#pragma unroll 1
  for (int c0 = 0; c0 < NCOLS; c0 += 4){
    float wn[4];
#pragma unroll
    for (int u=0;u<4;++u){
      int c = c0 + 4 + u;
      wn[u] = (c < NCOLS) ? W[c*DM + f] : 0.f;
    }
#pragma unroll
    for (int u=0;u<4;++u){
      if (c0 + u < NCOLS){
        const float2* src = reinterpret_cast<const float2*>(in_sm + (c0+u)*instride + base);
        float2 ww = make_float2(w[u], w[u]);
#pragma unroll
        for (int j=0;j<32;++j) acc[j] = ffma2(src[j], ww, acc[j]);
      }
    }
#pragma unroll
    for (int u=0;u<4;++u) w[u] = wn[u];
  }
}

// ======================= Kernel 1: KNN (top-16, stable) =====================
// grid = BB * (NN/128) = 128 blocks, 128 threads. All xyz of one batch in smem.
__global__ void __launch_bounds__(128,1) knn_kernel(const float* __restrict__ xyz)
{
  extern __shared__ float4 sp4[];
  int b  = blockIdx.x >> 5;
  int n0 = (blockIdx.x & 31) << 7;
  const float* xb = xyz + (size_t)b*NN*3;
  for (int i = threadIdx.x; i < NN; i += 128){
    float x = xb[i*3+0], y = xb[i*3+1], z = xb[i*3+2];
    sp4[i] = make_float4(x, y, z, x*x + y*y + z*z);
  }
  __syncthreads();

  int n = n0 + threadIdx.x;
  float4 me = sp4[n];
  float bd[16]; int bi[16];
#pragma unroll
  for (int j=0;j<16;++j){ bd[j] = 3.4e38f; bi[j] = 0; }

  for (int m = 0; m < NN; ++m){
    float4 o = sp4[m];
    float d = me.w + o.w - 2.f*(me.x*o.x + me.y*o.y + me.z*o.z);
    if (d < bd[15]){
      float cd = d; int ci = m;
#pragma unroll
      for (int j=0;j<16;++j){
        if (cd < bd[j]){
          float td = bd[j]; int ti = bi[j];
          bd[j] = cd; bi[j] = ci; cd = td; ci = ti;
        }
      }
    }
  }
  int* dst = g_knn + ((size_t)b*NN + n)*KK;
#pragma unroll
  for (int j=0;j<16;++j) dst[j] = bi[j];
}

// ======================= Kernel 2: x, q, k, v ===============================
// 128 rows per block, 256 threads: thread = (f = t&127, half = t>>7).
// smem: s_feat col-major [64][stride 130], s_x col-major [128][stride 130].
#define QKV_SMEM_FLOATS (64*130 + 128*130)

__device__ __forceinline__ void proj_store(const float* s_x, const float* __restrict__ W,
                                           float* __restrict__ G, int f, int base, size_t row0)
{
  float2 acc[32];
#pragma unroll
  for (int j=0;j<32;++j) acc[j] = make_float2(0.f, 0.f);
  gemm_acc<DM>(s_x, 130, W, f, base, acc);
#pragma unroll
  for (int j=0;j<32;++j){
    G[(row0 + base + 2*j  )*DM + f] = acc[j].x;
    G[(row0 + base + 2*j+1)*DM + f] = acc[j].y;
  }
}

__global__ void __launch_bounds__(256,1) qkv_kernel(
    const float* __restrict__ features,
    const float* __restrict__ fc1_w, const float* __restrict__ fc1_b,
    const float* __restrict__ wq_w,  const float* __restrict__ wk_w,
    const float* __restrict__ wv_w)
{
  extern __shared__ float smq[];
  float* s_feat = smq;            // 64 cols, stride 130
  float* s_x    = smq + 64*130;   // 128 cols, stride 130

  int f = threadIdx.x & 127, half = threadIdx.x >> 7, base = half << 6;
  size_t row0 = (size_t)blockIdx.x * 128;

  for (int i = threadIdx.x; i < 128*DP; i += 256){
    int r = i >> 6, c = i & 63;                      // coalesced read
    s_feat[c*130 + r] = features[(row0 + r)*DP + c]; // conflicted STS (tiny)
  }
  __syncthreads();

  { // x = feat @ fc1 + b
    float2 acc[32]; float bb = fc1_b[f];
#pragma unroll
    for (int j=0;j<32;++j) acc[j] = make_float2(bb, bb);
    gemm_acc<DP>(s_feat, 130, fc1_w, f, base, acc);
#pragma unroll
    for (int j=0;j<32;++j)
      *reinterpret_cast<float2*>(&s_x[f*130 + base + 2*j]) = acc[j];
  }
  __syncthreads();

  proj_store(s_x, wq_w, g_q, f, base, row0);
  proj_store(s_x, wk_w, g_k, f, base, row0);
  proj_store(s_x, wv_w, g_v, f, base, row0);
}

// ======================= Kernel 3: fused attention block ====================
// Tile = 8 points (128 neighbor-rows). 256 threads = (f, half). One block/SM.
#define OFF_A    0                 // 129 cols * stride 130
#define OFF_PE   (129*130)         // 128 * 130
#define OFF_H    (OFF_PE + 128*130)
#define OFF_Q    (OFF_H + 128*130 + 2)   // 8 * 132 (pad +2 keeps %4==0)
#define OFF_RES  (OFF_Q + 8*132)         // 8 * 128
#define OFF_RELP (OFF_RES + 8*128)       // 3 * 128
#define OFF_QN   (OFF_RELP + 3*128)      // 8
#define OFF_IDX  (OFF_QN + 8)            // 128 ints
#define MAIN_SMEM_FLOATS (OFF_IDX + 128)

__global__ void __launch_bounds__(256,1) main_kernel(
    const float* __restrict__ xyz,   const float* __restrict__ features,
    const float* __restrict__ fc2_w, const float* __restrict__ fc2_b,
    const float* __restrict__ d1_w,  const float* __restrict__ d1_b,
    const float* __restrict__ d2_w,  const float* __restrict__ d2_b,
    const float* __restrict__ g1_w,  const float* __restrict__ g1_b,
    const float* __restrict__ g2_w,  const float* __restrict__ g2_b,
    const float* __restrict__ sim_w, const float* __restrict__ sim_b,
    float* __restrict__ out_res, float* __restrict__ out_attn)
{
  extern __shared__ float sm[];
  float* s_a    = sm + OFF_A;
  float* s_pe   = sm + OFF_PE;
  float* s_h    = sm + OFF_H;
  float* s_q    = sm + OFF_Q;
  float* s_res  = sm + OFF_RES;
  float* s_relp = sm + OFF_RELP;
  float* s_qn   = sm + OFF_QN;
  int*   s_idx  = reinterpret_cast<int*>(sm + OFF_IDX);

  int tid  = threadIdx.x;
  int f    = tid & 127;
  int base = (tid >> 7) << 6;     // 0 or 64
  int tile = blockIdx.x;
  int b    = tile >> 9;           // 512 tiles per batch
  int n0   = (tile & 511) << 3;
  size_t bn0 = (size_t)b*NN + n0;

  // ---- Ph0: neighbor indices, rel_pos, q tile ----
  if (tid < 128){
    int r = tid, p = r >> 4, k = r & 15;
    int nb = g_knn[(bn0 + p)*KK + k];
    s_idx[r] = nb;
    const float* xn = xyz + (bn0 + p)*3;
    const float* xm = xyz + ((size_t)b*NN + nb)*3;
    s_relp[0*128 + r] = xn[0] - xm[0];
    s_relp[1*128 + r] = xn[1] - xm[1];
    s_relp[2*128 + r] = xn[2] - xm[2];
  }
  for (int i = tid; i < 8*DM; i += 256){
    int p = i >> 7, ff = i & 127;
    s_q[p*132 + ff] = g_q[(bn0 + p)*DM + ff];
  }
  __syncthreads();

  if (tid < 8){
    float s = 0.f;
    for (int c = 0; c < DM; ++c){ float v = s_q[tid*132 + c]; s += v*v; }
    s_qn[tid] = fmaxf(sqrtf(s), EPSN);
  }

  // ---- Ph1: P1 = relu(rel_pos @ d1 + b) -> s_a ----
  {
    float2 acc[32]; float bb = d1_b[f];
#pragma unroll
    for (int j=0;j<32;++j) acc[j] = make_float2(bb, bb);
    gemm_acc<3>(s_relp, 128, d1_w, f, base, acc);
#pragma unroll
    for (int j=0;j<32;++j){
      float2 v = acc[j];
      v.x = fmaxf(v.x, 0.f); v.y = fmaxf(v.y, 0.f);
      *reinterpret_cast<float2*>(&s_a[f*130 + base + 2*j]) = v;
    }
  }
  __syncthreads();

  // ---- Ph2: pos_enc = P1 @ d2 + b -> s_pe ----
  {
    float2 acc[32]; float bb = d2_b[f];
#pragma unroll
    for (int j=0;j<32;++j) acc[j] = make_float2(bb, bb);
    gemm_acc<DM>(s_a, 130, d2_w, f, base, acc);
#pragma unroll
    for (int j=0;j<32;++j)
      *reinterpret_cast<float2*>(&s_pe[f*130 + base + 2*j]) = acc[j];
  }
  __syncthreads();

  // ---- Ph3: build rel_qk rows into s_a (col 0 = cos-sim, 1..128 = q-k) ----
  {
    int wid = tid >> 5, lane = tid & 31;
    for (int r = wid*16; r < wid*16 + 16; ++r){
      int p  = r >> 4;
      int nb = s_idx[r];
      float4 k4 = *reinterpret_cast<const float4*>(g_k + ((size_t)b*NN + nb)*DM + lane*4);
      float4 q4 = *reinterpret_cast<const float4*>(&s_q[p*132 + lane*4]);
      float dt = k4.x*q4.x + k4.y*q4.y + k4.z*q4.z + k4.w*q4.w;
      float ks = k4.x*k4.x + k4.y*k4.y + k4.z*k4.z + k4.w*k4.w;
#pragma unroll
      for (int o=16;o;o>>=1){
        dt += __shfl_xor_sync(0xffffffffu, dt, o);
        ks += __shfl_xor_sync(0xffffffffu, ks, o);
      }
      float kn  = fmaxf(sqrtf(ks), EPSN);
      float sim = dt / (s_qn[p] * kn);
      if (lane == 0) s_a[r] = sim;
      s_a[(1 + lane*4 + 0)*130 + r] = q4.x - k4.x;
      s_a[(1 + lane*4 + 1)*130 + r] = q4.y - k4.y;
      s_a[(1 + lane*4 + 2)*130 + r] = q4.z - k4.z;
      s_a[(1 + lane*4 + 3)*130 + r] = q4.w - k4.w;
    }
  }
  __syncthreads();

  // ---- Ph4: t = (rel_qk @ sim_w + sim_b) + pos_enc -> s_h ----
  {
    float2 acc[32]; float bb = sim_b[f];
#pragma unroll
    for (int j=0;j<32;++j) acc[j] = make_float2(bb, bb);
    gemm_acc<DM+1>(s_a, 130, sim_w, f, base, acc);
#pragma unroll
    for (int j=0;j<32;++j){
      float2 pe = *reinterpret_cast<const float2*>(&s_pe[f*130 + base + 2*j]);
      float2 v  = acc[j];
      v.x += pe.x; v.y += pe.y;
      *reinterpret_cast<float2*>(&s_h[f*130 + base + 2*j]) = v;
    }
  }
  __syncthreads();

  // ---- Ph5: h = relu(t @ g1 + b) -> s_a ----
  {
    float2 acc[32]; float bb = g1_b[f];
#pragma unroll
    for (int j=0;j<32;++j) acc[j] = make_float2(bb, bb);
    gemm_acc<DM>(s_h, 130, g1_w, f, base, acc);
#pragma unroll
    for (int j=0;j<32;++j){
      float2 v = acc[j];
      v.x = fmaxf(v.x, 0.f); v.y = fmaxf(v.y, 0.f);
      *reinterpret_cast<float2*>(&s_a[f*130 + base + 2*j]) = v;
    }
  }
  __syncthreads();

  // ---- Ph6: logits = h @ g2 + b; softmax over k; attn out; res accumulate --
  {
    float2 acc[32]; float bb = g2_b[f];
#pragma unroll
    for (int j=0;j<32;++j) acc[j] = make_float2(bb, bb);
    gemm_acc<DM>(s_a, 130, g2_w, f, base, acc);

    const float inv_s = 0.08838834764831845f;  // 1/sqrt(128)
#pragma unroll
    for (int pi = 0; pi < 4; ++pi){
      int p = (base >> 4) + pi;
      float l[16];
#pragma unroll
      for (int j=0;j<8;++j){
        l[2*j]   = acc[pi*8 + j].x * inv_s;
        l[2*j+1] = acc[pi*8 + j].y * inv_s;
      }
      float m = l[0];
#pragma unroll
      for (int k=1;k<16;++k) m = fmaxf(m, l[k]);
      float s = 0.f;
#pragma unroll
      for (int k=0;k<16;++k){ l[k] = __expf(l[k] - m); s += l[k]; }
      float rs = 1.f / s;

      float racc = 0.f;
      size_t gn = bn0 + p;
      float* ao = out_attn + (gn*KK)*DM + f;
#pragma unroll
      for (int k=0;k<16;++k){
        int r = p*16 + k;
        float a = l[k] * rs;
        ao[k*DM] = a;
        float vv = g_v[((size_t)b*NN + s_idx[r])*DM + f];
        racc += a * (vv + s_pe[f*130 + r]);
      }
      s_res[p*DM + f] = racc;
    }
  }
  __syncthreads();

  // ---- Ph7: out = res @ fc2 + b + features ----
  {
    int o  = tid & 63;
    int pg = tid >> 6;           // 0..3 -> points pg and pg+4
    float a0 = fc2_b[o], a1 = a0;
    int p0 = pg, p1 = pg + 4;
    for (int c = 0; c < DM; ++c){
      float w = fc2_w[c*DP + o];
      a0 += s_res[p0*DM + c] * w;
      a1 += s_res[p1*DM + c] * w;
    }
    out_res[(bn0 + p0)*DP + o] = a0 + features[(bn0 + p0)*DP + o];
    out_res[(bn0 + p1)*DP + o] = a1 + features[(bn0 + p1)*DP + o];
  }
}

// ============================ launcher ======================================
extern "C" void kernel_launch(void* const* d_in, const int* in_sizes, int n_in,
                              void* d_out, int out_size)
{
  (void)in_sizes; (void)n_in; (void)out_size;
  const float* xyz      = (const float*)d_in[0];
  const float* features = (const float*)d_in[1];
  const float* fc1_w    = (const float*)d_in[2];
  const float* fc1_b    = (const float*)d_in[3];
  const float* fc2_w    = (const float*)d_in[4];
  const float* fc2_b    = (const float*)d_in[5];
  const float* d1_w     = (const float*)d_in[6];
  const float* d1_b     = (const float*)d_in[7];
  const float* d2_w     = (const float*)d_in[8];
  const float* d2_b     = (const float*)d_in[9];
  const float* g1_w     = (const float*)d_in[10];
  const float* g1_b     = (const float*)d_in[11];
  const float* g2_w     = (const float*)d_in[12];
  const float* g2_b     = (const float*)d_in[13];
  const float* wq_w     = (const float*)d_in[14];
  const float* wk_w     = (const float*)d_in[15];
  const float* wv_w     = (const float*)d_in[16];
  const float* sim_w    = (const float*)d_in[17];
  const float* sim_b    = (const float*)d_in[18];

  float* out      = (float*)d_out;
  float* out_res  = out;                        // (B,N,DP)
  float* out_attn = out + (size_t)BB*NN*DP;     // (B,N,K,DM)

  const int knn_smem  = NN * sizeof(float4);                 // 64 KB
  const int qkv_smem  = QKV_SMEM_FLOATS * sizeof(float);     // ~97.5 KB
  const int main_smem = MAIN_SMEM_FLOATS * sizeof(float);    // ~205.7 KB

  cudaFuncSetAttribute(knn_kernel,  cudaFuncAttributeMaxDynamicSharedMemorySize, knn_smem);
  cudaFuncSetAttribute(qkv_kernel,  cudaFuncAttributeMaxDynamicSharedMemorySize, qkv_smem);
  cudaFuncSetAttribute(main_kernel, cudaFuncAttributeMaxDynamicSharedMemorySize, main_smem);

  knn_kernel<<<BB*(NN/128), 128, knn_smem>>>(xyz);
  qkv_kernel<<<(BB*NN)/128, 256, qkv_smem>>>(features, fc1_w, fc1_b, wq_w, wk_w, wv_w);
  main_kernel<<<(BB*NN)/8, 256, main_smem>>>(
      xyz, features, fc2_w, fc2_b, d1_w, d1_b, d2_w, d2_b,
      g1_w, g1_b, g2_w, g2_b, sim_w, sim_b, out_res, out_attn);
}

// round 4
// speedup vs baseline: 1.0498x; 1.0498x over previous
#include <cuda_runtime.h>
#include <cstdint>

#define BB 4
#define NN 4096
#define KK 16
#define DP 64
#define DM 128
#define EPSN 1e-8f

// ---------------- scratch (device globals; no allocation allowed) ----------
__device__ float g_q[BB*NN*DM];     // 8 MB
__device__ float g_k[BB*NN*DM];     // 8 MB
__device__ float g_v[BB*NN*DM];     // 8 MB
__device__ int   g_knn[BB*NN*KK];   // 1 MB

// ---------------- packed fp32x2 FMA (Blackwell FFMA2) ----------------------
__device__ __forceinline__ float2 ffma2(float2 a, float2 b, float2 c){
  float2 d;
  asm("fma.rn.f32x2 %0, %1, %2, %3;"
      : "=l"(reinterpret_cast<unsigned long long&>(d))
      : "l"(reinterpret_cast<unsigned long long&>(a)),
        "l"(reinterpret_cast<unsigned long long&>(b)),
        "l"(reinterpret_cast<unsigned long long&>(c)));
  return d;
}

// Core GEMM: input 128 rows col-major in smem (stride even), W row-major
// [NCOLS][DM]. Thread (cg = tid&31, rg = tid>>5) computes cols {cg+32q} for
// rows [16*rg, 16*rg+16) as 8 row-pair float2 accumulators x 4 cols.
// Row loads are warp-uniform (broadcast LDS.64); weight loads coalesced LDG,
// prefetched one column ahead.
template<int NCOLS>
__device__ __forceinline__ void gemm4(const float* __restrict__ S, int stride,
                                      const float* __restrict__ W,
                                      int cg, int rg, float2 acc[8][4])
{
  const float* src = S + 16*rg;
  float w[4];
#pragma unroll
  for (int q=0;q<4;++q) w[q] = W[cg + 32*q];
#pragma unroll 2
  for (int c=0;c<NCOLS;++c){
    float wn[4];
    if (c+1 < NCOLS){
#pragma unroll
      for (int q=0;q<4;++q) wn[q] = W[(c+1)*DM + cg + 32*q];
    }
    float2 r[8];
#pragma unroll
    for (int j=0;j<8;++j)
      r[j] = *reinterpret_cast<const float2*>(src + c*stride + 2*j);
#pragma unroll
    for (int j=0;j<8;++j){
#pragma unroll
      for (int q=0;q<4;++q)
        acc[j][q] = ffma2(r[j], make_float2(w[q], w[q]), acc[j][q]);
    }
#pragma unroll
    for (int q=0;q<4;++q) w[q] = wn[q];
  }
}

__device__ __forceinline__ void acc_init(float2 acc[8][4], const float* __restrict__ bias, int cg){
#pragma unroll
  for (int q=0;q<4;++q){
    float bb = bias[cg + 32*q];
#pragma unroll
    for (int j=0;j<8;++j) acc[j][q] = make_float2(bb, bb);
  }
}

// store to col-major smem [col*130 + row]
__device__ __forceinline__ void acc_store(float* dst, const float2 acc[8][4], int cg, int rg, bool relu){
#pragma unroll
  for (int q=0;q<4;++q){
    int col = cg + 32*q;
#pragma unroll
    for (int j=0;j<8;++j){
      float2 v = acc[j][q];
      if (relu){ v.x = fmaxf(v.x, 0.f); v.y = fmaxf(v.y, 0.f); }
      *reinterpret_cast<float2*>(&dst[col*130 + 16*rg + 2*j]) = v;
    }
  }
}

// ======================= Kernel 1: KNN (top-16, stable) =====================
// 128 blocks x 512 threads. 4 threads per point, each scans a contiguous
// 1024-chunk (stability: strict < keeps earlier index first within chunk),
// then the 4 sorted lists are merged lexicographically by (d, idx).
__global__ void __launch_bounds__(512,1) knn_kernel(const float* __restrict__ xyz)
{
  extern __shared__ float4 sp4[];                   // NN float4 = 64 KB
  float* s_d = reinterpret_cast<float*>(sp4 + NN);  // [64][128] = 32 KB
  int*   s_i = reinterpret_cast<int*>(s_d + 64*128);// [64][128] = 32 KB

  int b  = blockIdx.x >> 5;
  int n0 = (blockIdx.x & 31) << 7;
  const float* xb = xyz + (size_t)b*NN*3;
  for (int i = threadIdx.x; i < NN; i += 512){
    float x = xb[i*3+0], y = xb[i*3+1], z = xb[i*3+2];
    sp4[i] = make_float4(x, y, z, x*x + y*y + z*z);
  }
  __syncthreads();

  int p = threadIdx.x & 127, h = threadIdx.x >> 7;
  float4 me = sp4[n0 + p];
  float bd[16]; int bi[16];
#pragma unroll
  for (int j=0;j<16;++j){ bd[j] = 3.4e38f; bi[j] = 0x7fffffff; }

  int m0 = h << 10;
#pragma unroll 1
  for (int m = m0; m < m0 + 1024; m += 2){
    float4 o0 = sp4[m], o1 = sp4[m+1];
    float d0 = me.w + o0.w - 2.f*(me.x*o0.x + me.y*o0.y + me.z*o0.z);
    float d1 = me.w + o1.w - 2.f*(me.x*o1.x + me.y*o1.y + me.z*o1.z);
    if (d0 < bd[15]){
      float cd = d0; int ci = m;
#pragma unroll
      for (int j=0;j<16;++j){
        if (cd < bd[j]){ float td=bd[j]; int ti=bi[j]; bd[j]=cd; bi[j]=ci; cd=td; ci=ti; }
      }
    }
    if (d1 < bd[15]){
      float cd = d1; int ci = m+1;
#pragma unroll
      for (int j=0;j<16;++j){
        if (cd < bd[j]){ float td=bd[j]; int ti=bi[j]; bd[j]=cd; bi[j]=ci; cd=td; ci=ti; }
      }
    }
  }
#pragma unroll
  for (int j=0;j<16;++j){
    s_d[(h*16 + j)*128 + p] = bd[j];
    s_i[(h*16 + j)*128 + p] = bi[j];
  }
  __syncthreads();

  if (threadIdx.x < 128){
    int pp = threadIdx.x;
    float fd[16]; int fi[16];
#pragma unroll
    for (int j=0;j<16;++j){ fd[j] = 3.4e38f; fi[j] = 0x7fffffff; }
#pragma unroll 1
    for (int e = 0; e < 64; ++e){
      float d = s_d[e*128 + pp];
      int   i = s_i[e*128 + pp];
      if (d < fd[15] || (d == fd[15] && i < fi[15])){
        float cd = d; int ci = i;
#pragma unroll
        for (int j=0;j<16;++j){
          if (cd < fd[j] || (cd == fd[j] && ci < fi[j])){
            float td=fd[j]; int ti=fi[j]; fd[j]=cd; fi[j]=ci; cd=td; ci=ti;
          }
        }
      }
    }
    int* dst = g_knn + ((size_t)b*NN + n0 + pp)*KK;
#pragma unroll
    for (int j=0;j<16;++j) dst[j] = fi[j];
  }
}

// ======================= Kernel 2: x, q, k, v ===============================
#define QKV_SMEM_FLOATS (64*130 + 128*130)

__global__ void __launch_bounds__(256,1) qkv_kernel(
    const float* __restrict__ features,
    const float* __restrict__ fc1_w, const float* __restrict__ fc1_b,
    const float* __restrict__ wq_w,  const float* __restrict__ wk_w,
    const float* __restrict__ wv_w)
{
  extern __shared__ float smq[];
  float* s_feat = smq;            // 64 cols, stride 130
  float* s_x    = smq + 64*130;   // 128 cols, stride 130

  int cg = threadIdx.x & 31, rg = threadIdx.x >> 5;
  size_t row0 = (size_t)blockIdx.x * 128;

  for (int i = threadIdx.x; i < 128*DP; i += 256){
    int r = i >> 6, c = i & 63;
    s_feat[c*130 + r] = features[(row0 + r)*DP + c];
  }
  __syncthreads();

  { // x = feat @ fc1 + b -> s_x
    float2 acc[8][4];
    acc_init(acc, fc1_b, cg);
    gemm4<DP>(s_feat, 130, fc1_w, cg, rg, acc);
    acc_store(s_x, acc, cg, rg, false);
  }
  __syncthreads();

  const float* Ws[3] = { wq_w, wk_w, wv_w };
  float* Gs[3];
  Gs[0] = g_q; Gs[1] = g_k; Gs[2] = g_v;
#pragma unroll 1
  for (int t = 0; t < 3; ++t){
    float2 acc[8][4];
#pragma unroll
    for (int q=0;q<4;++q)
#pragma unroll
      for (int j=0;j<8;++j) acc[j][q] = make_float2(0.f, 0.f);
    gemm4<DM>(s_x, 130, Ws[t], cg, rg, acc);
    float* G = Gs[t];
#pragma unroll
    for (int j=0;j<8;++j){
      int r0 = 16*rg + 2*j;
#pragma unroll
      for (int q=0;q<4;++q){
        int col = cg + 32*q;
        G[(row0 + r0    )*DM + col] = acc[j][q].x;
        G[(row0 + r0 + 1)*DM + col] = acc[j][q].y;
      }
    }
  }
}

// ======================= Kernel 3: fused attention block ====================
#define OFF_A    0                       // 129 cols * 130
#define OFF_PE   (129*130)               // 128 * 130
#define OFF_H    (OFF_PE + 128*130)      // 128 * 130
#define OFF_Q    (OFF_H + 128*130 + 2)   // 8 * 132
#define OFF_RES  (OFF_Q + 8*132)         // 8 * 128
#define OFF_RELP (OFF_RES + 8*128)       // 3 * 128
#define OFF_QN   (OFF_RELP + 3*128)      // 8
#define OFF_IDX  (OFF_QN + 8)            // 128 ints
#define MAIN_SMEM_FLOATS (OFF_IDX + 128)

__global__ void __launch_bounds__(256,1) main_kernel(
    const float* __restrict__ xyz,   const float* __restrict__ features,
    const float* __restrict__ fc2_w, const float* __restrict__ fc2_b,
    const float* __restrict__ d1_w,  const float* __restrict__ d1_b,
    const float* __restrict__ d2_w,  const float* __restrict__ d2_b,
    const float* __restrict__ g1_w,  const float* __restrict__ g1_b,
    const float* __restrict__ g2_w,  const float* __restrict__ g2_b,
    const float* __restrict__ sim_w, const float* __restrict__ sim_b,
    float* __restrict__ out_res, float* __restrict__ out_attn)
{
  extern __shared__ float sm[];
  float* s_a    = sm + OFF_A;
  float* s_pe   = sm + OFF_PE;
  float* s_h    = sm + OFF_H;
  float* s_q    = sm + OFF_Q;
  float* s_res  = sm + OFF_RES;
  float* s_relp = sm + OFF_RELP;
  float* s_qn   = sm + OFF_QN;
  int*   s_idx  = reinterpret_cast<int*>(sm + OFF_IDX);

  int tid  = threadIdx.x;
  int cg   = tid & 31;
  int rg   = tid >> 5;                 // 0..7 == point within tile
  int lane = tid & 31;
  int tile = blockIdx.x;
  int b    = tile >> 9;
  int n0   = (tile & 511) << 3;
  size_t bn0 = (size_t)b*NN + n0;

  // ---- Ph0: neighbor indices, rel_pos, q tile ----
  if (tid < 128){
    int r = tid, p = r >> 4, k = r & 15;
    int nb = g_knn[(bn0 + p)*KK + k];
    s_idx[r] = nb;
    const float* xn = xyz + (bn0 + p)*3;
    const float* xm = xyz + ((size_t)b*NN + nb)*3;
    s_relp[0*128 + r] = xn[0] - xm[0];
    s_relp[1*128 + r] = xn[1] - xm[1];
    s_relp[2*128 + r] = xn[2] - xm[2];
  }
  for (int i = tid; i < 8*DM; i += 256){
    int p = i >> 7, ff = i & 127;
    s_q[p*132 + ff] = g_q[(bn0 + p)*DM + ff];
  }
  __syncthreads();

  { // qn[p] by warp p
    float4 q4 = *reinterpret_cast<const float4*>(&s_q[rg*132 + lane*4]);
    float s = q4.x*q4.x + q4.y*q4.y + q4.z*q4.z + q4.w*q4.w;
#pragma unroll
    for (int o=16;o;o>>=1) s += __shfl_xor_sync(0xffffffffu, s, o);
    if (lane == 0) s_qn[rg] = fmaxf(sqrtf(s), EPSN);
  }

  // ---- Ph1: P1 = relu(rel_pos @ d1 + b) -> s_a ----
  {
    float2 acc[8][4];
    acc_init(acc, d1_b, cg);
    gemm4<3>(s_relp, 128, d1_w, cg, rg, acc);
    acc_store(s_a, acc, cg, rg, true);
  }
  __syncthreads();

  // ---- Ph2: pos_enc = P1 @ d2 + b -> s_pe ----
  {
    float2 acc[8][4];
    acc_init(acc, d2_b, cg);
    gemm4<DM>(s_a, 130, d2_w, cg, rg, acc);
    acc_store(s_pe, acc, cg, rg, false);
  }
  __syncthreads();

  // ---- Ph3: build rel_qk into s_a (col 0 = cos-sim, 1..128 = q-k) ----
  {
    int wid = rg;
#pragma unroll 1
    for (int r = wid*16; r < wid*16 + 16; ++r){
      int p  = r >> 4;
      int nb = s_idx[r];
      float4 k4 = *reinterpret_cast<const float4*>(g_k + ((size_t)b*NN + nb)*DM + lane*4);
      float4 q4 = *reinterpret_cast<const float4*>(&s_q[p*132 + lane*4]);
      float dt = k4.x*q4.x + k4.y*q4.y + k4.z*q4.z + k4.w*q4.w;
      float ks = k4.x*k4.x + k4.y*k4.y + k4.z*k4.z + k4.w*k4.w;
#pragma unroll
      for (int o=16;o;o>>=1){
        dt += __shfl_xor_sync(0xffffffffu, dt, o);
        ks += __shfl_xor_sync(0xffffffffu, ks, o);
      }
      float kn  = fmaxf(sqrtf(ks), EPSN);
      float sim = dt / (s_qn[p] * kn);
      if (lane == 0) s_a[r] = sim;
      s_a[(1 + lane*4 + 0)*130 + r] = q4.x - k4.x;
      s_a[(1 + lane*4 + 1)*130 + r] = q4.y - k4.y;
      s_a[(1 + lane*4 + 2)*130 + r] = q4.z - k4.z;
      s_a[(1 + lane*4 + 3)*130 + r] = q4.w - k4.w;
    }
  }
  __syncthreads();

  // ---- Ph4: t = (rel_qk @ sim_w + sim_b) + pos_enc -> s_h ----
  {
    float2 acc[8][4];
    acc_init(acc, sim_b, cg);
    gemm4<DM+1>(s_a, 130, sim_w, cg, rg, acc);
#pragma unroll
    for (int q=0;q<4;++q){
      int col = cg + 32*q;
#pragma unroll
      for (int j=0;j<8;++j){
        float2 pe = *reinterpret_cast<const float2*>(&s_pe[col*130 + 16*rg + 2*j]);
        float2 v  = acc[j][q];
        v.x += pe.x; v.y += pe.y;
        *reinterpret_cast<float2*>(&s_h[col*130 + 16*rg + 2*j]) = v;
      }
    }
  }
  __syncthreads();

  // ---- Ph5: h = relu(t @ g1 + b) -> s_a ----
  {
    float2 acc[8][4];
    acc_init(acc, g1_b, cg);
    gemm4<DM>(s_h, 130, g1_w, cg, rg, acc);
    acc_store(s_a, acc, cg, rg, true);
  }
  __syncthreads();

  // ---- Ph6: logits = h @ g2 + b; per-thread softmax over k; attn; res ----
  {
    float2 acc[8][4];
    acc_init(acc, g2_b, cg);
    gemm4<DM>(s_a, 130, g2_w, cg, rg, acc);

    const float inv_s = 0.08838834764831845f;  // 1/sqrt(128)
    int p = rg;
    size_t gn = bn0 + p;
    float racc[4] = {0.f, 0.f, 0.f, 0.f};
#pragma unroll
    for (int q=0;q<4;++q){
      int col = cg + 32*q;
      float l[16];
#pragma unroll
      for (int j=0;j<8;++j){
        l[2*j]   = acc[j][q].x * inv_s;
        l[2*j+1] = acc[j][q].y * inv_s;
      }
      float m = l[0];
#pragma unroll
      for (int k=1;k<16;++k) m = fmaxf(m, l[k]);
      float s = 0.f;
#pragma unroll
      for (int k=0;k<16;++k){ l[k] = expf(l[k] - m); s += l[k]; }
      float rs = 1.f / s;

      float* ao = out_attn + (gn*KK)*DM + col;
#pragma unroll
      for (int k=0;k<16;++k){
        int r = p*16 + k;
        float a = l[k] * rs;
        ao[k*DM] = a;
        float vv = g_v[((size_t)b*NN + s_idx[r])*DM + col];
        racc[q] += a * (vv + s_pe[col*130 + r]);
      }
    }
#pragma unroll
    for (int q=0;q<4;++q) s_res[p*DM + cg + 32*q] = racc[q];
  }
  __syncthreads();

  // ---- Ph7: out = res @ fc2 + b + features ----
  {
    int o  = tid & 63;
    int pg = tid >> 6;
    float a0 = fc2_b[o], a1 = a0;
    int p0 = pg, p1 = pg + 4;
#pragma unroll 4
    for (int c = 0; c < DM; ++c){
      float w = fc2_w[c*DP + o];
      a0 += s_res[p0*DM + c] * w;
      a1 += s_res[p1*DM + c] * w;
    }
    out_res[(bn0 + p0)*DP + o] = a0 + features[(bn0 + p0)*DP + o];
    out_res[(bn0 + p1)*DP + o] = a1 + features[(bn0 + p1)*DP + o];
  }
}

// ============================ launcher ======================================
extern "C" void kernel_launch(void* const* d_in, const int* in_sizes, int n_in,
                              void* d_out, int out_size)
{
  (void)in_sizes; (void)n_in; (void)out_size;
  const float* xyz      = (const float*)d_in[0];
  const float* features = (const float*)d_in[1];
  const float* fc1_w    = (const float*)d_in[2];
  const float* fc1_b    = (const float*)d_in[3];
  const float* fc2_w    = (const float*)d_in[4];
  const float* fc2_b    = (const float*)d_in[5];
  const float* d1_w     = (const float*)d_in[6];
  const float* d1_b     = (const float*)d_in[7];
  const float* d2_w     = (const float*)d_in[8];
  const float* d2_b     = (const float*)d_in[9];
  const float* g1_w     = (const float*)d_in[10];
  const float* g1_b     = (const float*)d_in[11];
  const float* g2_w     = (const float*)d_in[12];
  const float* g2_b     = (const float*)d_in[13];
  const float* wq_w     = (const float*)d_in[14];
  const float* wk_w     = (const float*)d_in[15];
  const float* wv_w     = (const float*)d_in[16];
  const float* sim_w    = (const float*)d_in[17];
  const float* sim_b    = (const float*)d_in[18];

  float* out      = (float*)d_out;
  float* out_res  = out;                        // (B,N,DP)
  float* out_attn = out + (size_t)BB*NN*DP;     // (B,N,K,DM)

  const int knn_smem  = NN*sizeof(float4) + 64*128*8;        // 128 KB
  const int qkv_smem  = QKV_SMEM_FLOATS * sizeof(float);     // ~97.5 KB
  const int main_smem = MAIN_SMEM_FLOATS * sizeof(float);    // ~205.7 KB

  cudaFuncSetAttribute(knn_kernel,  cudaFuncAttributeMaxDynamicSharedMemorySize, knn_smem);
  cudaFuncSetAttribute(qkv_kernel,  cudaFuncAttributeMaxDynamicSharedMemorySize, qkv_smem);
  cudaFuncSetAttribute(main_kernel, cudaFuncAttributeMaxDynamicSharedMemorySize, main_smem);

  knn_kernel<<<BB*(NN/128), 512, knn_smem>>>(xyz);
  qkv_kernel<<<(BB*NN)/128, 256, qkv_smem>>>(features, fc1_w, fc1_b, wq_w, wk_w, wv_w);
  main_kernel<<<(BB*NN)/8, 256, main_smem>>>(
      xyz, features, fc2_w, fc2_b, d1_w, d1_b, d2_w, d2_b,
      g1_w, g1_b, g2_w, g2_b, sim_w, sim_b, out_res, out_attn);
}